// round 9
// baseline (speedup 1.0000x reference)
#include <cuda_runtime.h>
#include <math.h>

#define MARGIN 0.02f
#define EPS 1e-12f
#define K_INST 4
#define DIM 128
#define NMAX 4096

#define TM 64
#define TN 64
#define KC 16
#define NKP 8           // k-pairs per stage
#define ROWF 128        // floats per kpair row: 64 float2
#define STAGE_F 2048    // floats per stage: A 1024 + B 1024 (8 KB)
#define TTILES 64       // n / TM
#define NBLOCKS 2080    // TTILES*(TTILES+1)/2
#define NSTAGES 8       // DIM / KC
#define THREADS 256

__device__ double g_tot;
__device__ double g_neg;
__device__ unsigned long long g_nv;
__device__ unsigned int g_ticket;
__device__ int   g_pa[NMAX];
__device__ float g_posp[NMAX * 3];    // pos_dist + MARGIN (plain stores, replay-safe)
__device__ float g_sqn[NMAX];

__device__ __forceinline__ float fsqrt_approx(float x) {
    float r;
    asm("sqrt.approx.f32 %0, %1;" : "=f"(r) : "f"(x));
    return r;
}

#define FFMA2(d, a, b, c) \
    asm("fma.rn.f32x2 %0, %1, %2, %3;" : "=l"(d) : "l"(a), "l"(b), "l"(c))

#define UNPACK2(lo, hi, v) \
    asm("mov.b64 {%0, %1}, %2;" : "=f"(lo), "=f"(hi) : "l"(v))

// ---------------------------------------------------------------------------
__global__ void pos_kernel(const float* __restrict__ X, int n) {
    int gwarp = (blockIdx.x * blockDim.x + threadIdx.x) >> 5;
    int lane  = threadIdx.x & 31;
    if (blockIdx.x == 0 && threadIdx.x == 0) {
        g_tot = 0.0; g_neg = 0.0; g_nv = 0ULL; g_ticket = 0u;
    }
    if (gwarp >= n) return;
    int i = gwarp;
    if (lane == 1) g_pa[i] = 0;

    float4 a = ((const float4*)(X + (size_t)i * DIM))[lane];
    float selfsq = a.x * a.x + a.y * a.y + a.z * a.z + a.w * a.w;

    int cs = i & ~(K_INST - 1);
    float dd[K_INST - 1];
    int idx = 0;
    #pragma unroll
    for (int q = 0; q < K_INST; q++) {
        if (cs + q == i) continue;
        float4 b = ((const float4*)(X + (size_t)(cs + q) * DIM))[lane];
        float dx = a.x - b.x, dy = a.y - b.y, dz = a.z - b.z, dw = a.w - b.w;
        dd[idx++] = dx * dx + dy * dy + dz * dz + dw * dw;
    }

    #pragma unroll
    for (int o = 16; o; o >>= 1) {
        selfsq += __shfl_xor_sync(0xFFFFFFFFu, selfsq, o);
        #pragma unroll
        for (int p = 0; p < K_INST - 1; p++)
            dd[p] += __shfl_xor_sync(0xFFFFFFFFu, dd[p], o);
    }

    if (lane == 0) {
        g_sqn[i] = selfsq;
        #pragma unroll
        for (int p = 0; p < K_INST - 1; p++) {
            float d = fsqrt_approx(fmaxf(dd[p], EPS));
            g_posp[i * 3 + p] = d + MARGIN;
        }
    }
}

// ---------------------------------------------------------------------------
// Upper-triangular 64x64 Gram tiles. K-packed FFMA2, 4x4 micro-tiles,
// 256 threads, 3 CTAs/SM, double-buffered register-prefetch pipeline.
__global__ __launch_bounds__(THREADS, 3) void main_kernel(const float* __restrict__ X,
                                                          float* __restrict__ out, int n) {
    // Triangular tile decode
    int bid = blockIdx.x;
    float tf = 2.0f * TTILES + 1.0f;
    int rowT = (int)((tf - sqrtf(tf * tf - 8.0f * (float)bid)) * 0.5f);
    while ((rowT + 1) * TTILES - ((rowT + 1) * rowT) / 2 <= bid) rowT++;
    while (rowT * TTILES - (rowT * (rowT - 1)) / 2 > bid) rowT--;
    int colT = rowT + (bid - (rowT * TTILES - (rowT * (rowT - 1)) / 2));

    __shared__ __align__(16) float sm[2 * STAGE_F];   // 16 KB

    int tid = threadIdx.x;
    int tx = tid & 15;       // n-dim: cols tx*4 .. +3
    int ty = tid >> 4;       // m-dim: rows ty*4 .. +3
    int rowBase = rowT * TM;
    int colBase = colT * TN;
    bool offdiag = (colT != rowT);

    // Loader: one float4 per matrix per thread per stage (2 kpairs, row lr)
    int c4 = tid & 3;
    int lr = tid >> 2;       // 0..63
    const float* __restrict__ Arow = X + (size_t)(rowBase + lr) * DIM + c4 * 4;
    const float* __restrict__ Brow = X + (size_t)(colBase + lr) * DIM + c4 * 4;

    int su  = lr >> 1;       // 16B unit 0..31 (unit holds rows 2u, 2u+1)
    int ssub = lr & 1;
    int kp0 = c4 * 2;
    int kp1 = c4 * 2 + 1;

    float4 va, wa;

    unsigned long long acc[4][4];   // k-packed (even,odd) partial sums
    #pragma unroll
    for (int a = 0; a < 4; a++)
        #pragma unroll
        for (int b = 0; b < 4; b++) acc[a][b] = 0ULL;

#define LD_STAGE(s)                                                            \
    do {                                                                       \
        int off = (s) * KC;                                                    \
        va = *(const float4*)(Arow + off);                                     \
        wa = *(const float4*)(Brow + off);                                     \
    } while (0)

#define ST_STAGE(buf)                                                          \
    do {                                                                       \
        float* sA = sm + (buf) * STAGE_F;                                      \
        float* sB = sA + NKP * ROWF;                                           \
        *(float2*)&sA[kp0 * ROWF + ((su ^ kp0) & 31) * 4 + ssub * 2] =         \
            make_float2(va.x, va.y);                                           \
        *(float2*)&sA[kp1 * ROWF + ((su ^ kp1) & 31) * 4 + ssub * 2] =         \
            make_float2(va.z, va.w);                                           \
        *(float2*)&sB[kp0 * ROWF + ((su ^ kp0) & 31) * 4 + ssub * 2] =         \
            make_float2(wa.x, wa.y);                                           \
        *(float2*)&sB[kp1 * ROWF + ((su ^ kp1) & 31) * 4 + ssub * 2] =         \
            make_float2(wa.z, wa.w);                                           \
    } while (0)

    LD_STAGE(0);
    ST_STAGE(0);
    LD_STAGE(1);
    __syncthreads();

    int p = 0;
    #pragma unroll 1
    for (int st = 0; st < NSTAGES; st++) {
        const float* sA = sm + p * STAGE_F;
        const float* sB = sA + NKP * ROWF;

        #pragma unroll
        for (int kp = 0; kp < NKP; kp++) {
            // A: units ty*2+j (rows ty*4+2j, +1), stored at pos (unit^kp)
            unsigned long long ap[4], bp[4];
            #pragma unroll
            for (int j = 0; j < 2; j++) {
                ulonglong2 t = *(const ulonglong2*)
                    &sA[kp * ROWF + (((ty * 2 + j) ^ kp) & 31) * 4];
                ap[j * 2 + 0] = t.x;
                ap[j * 2 + 1] = t.y;
                ulonglong2 u = *(const ulonglong2*)
                    &sB[kp * ROWF + (((tx * 2 + j) ^ kp) & 31) * 4];
                bp[j * 2 + 0] = u.x;
                bp[j * 2 + 1] = u.y;
            }
            #pragma unroll
            for (int mi = 0; mi < 4; mi++)
                #pragma unroll
                for (int ni = 0; ni < 4; ni++)
                    FFMA2(acc[mi][ni], ap[mi], bp[ni], acc[mi][ni]);
        }

        if (st < NSTAGES - 1) {
            ST_STAGE(p ^ 1);
            __syncthreads();
            if (st < NSTAGES - 2) LD_STAGE(st + 2);
            p ^= 1;
        }
    }
    __syncthreads();   // mainloop buffers dead; epilogue aliases sm below

    // Aliased epilogue scratch
    double* psh      = (double*)sm;             // 256 doubles
    int*    zsh      = (int*)(sm + 512);        // 256 ints
    int*    colCnt   = (int*)(sm + 768);        // 64
    float*  redT     = sm + 832;                // 8
    float*  redN     = sm + 840;                // 8
    int*    redC     = (int*)(sm + 848);        // 8
    int*    lastFlag = (int*)(sm + 856);

    if (tid < TN) colCnt[tid] = 0;

    // Collapse k-packed accumulators
    float accf[4][4];
    #pragma unroll
    for (int mi = 0; mi < 4; mi++)
        #pragma unroll
        for (int ni = 0; ni < 4; ni++) {
            float lo, hi;
            UNPACK2(lo, hi, acc[mi][ni]);
            accf[mi][ni] = lo + hi;
        }

    // Per-thread metadata direct from global (L2-hot)
    float sqa[4], sqb[4], pa[12], pb[12];
    {
        float4 t0 = *(const float4*)&g_sqn[rowBase + ty * 4];
        float4 u0 = *(const float4*)&g_sqn[colBase + tx * 4];
        #pragma unroll
        for (int q = 0; q < 4; q++) { sqa[q] = (&t0.x)[q]; sqb[q] = (&u0.x)[q]; }
        const float4* p0 = (const float4*)&g_posp[(rowBase + ty * 4) * 3];
        const float4* p1 = (const float4*)&g_posp[(colBase + tx * 4) * 3];
        #pragma unroll
        for (int j = 0; j < 3; j++) {
            float4 v = p0[j];
            float4 w = p1[j];
            #pragma unroll
            for (int q = 0; q < 4; q++) { pa[j * 4 + q] = (&v.x)[q]; pb[j * 4 + q] = (&w.x)[q]; }
        }
    }
    __syncthreads();   // colCnt zeroed before atomics

    float tsum = 0.0f, nsum = 0.0f;
    int cr[4] = {0, 0, 0, 0};
    int cc[4] = {0, 0, 0, 0};

    #pragma unroll
    for (int mi = 0; mi < 4; mi++) {
        int i = rowBase + ty * 4 + mi;
        int ci = i >> 2;
        float sqi = sqa[mi];
        float pp0 = pa[mi * 3], pp1 = pa[mi * 3 + 1], pp2 = pa[mi * 3 + 2];
        #pragma unroll
        for (int ni = 0; ni < 4; ni++) {
            int j = colBase + tx * 4 + ni;
            if (!offdiag && (j >> 2) == ci) continue;
            float d2 = sqi + sqb[ni] - 2.0f * accf[mi][ni];
            float d  = fsqrt_approx(fmaxf(d2, EPS));
            float t0 = pp0 - d, t1 = pp1 - d, t2 = pp2 - d;
            if (t0 > 0.0f) { tsum += t0; cr[mi]++; }
            if (t1 > 0.0f) { tsum += t1; cr[mi]++; }
            if (t2 > 0.0f) { tsum += t2; cr[mi]++; }
            if (offdiag) {
                nsum += 2.0f * d;
                float u0 = pb[ni * 3] - d, u1 = pb[ni * 3 + 1] - d, u2 = pb[ni * 3 + 2] - d;
                if (u0 > 0.0f) { tsum += u0; cc[ni]++; }
                if (u1 > 0.0f) { tsum += u1; cc[ni]++; }
                if (u2 > 0.0f) { tsum += u2; cc[ni]++; }
            } else {
                nsum += d;
            }
        }
    }

    int cnt = 0;
    #pragma unroll
    for (int z = 0; z < 4; z++) cnt += cr[z] + cc[z];

    // Row-anchor counts: reduce over 16 tx lanes
    #pragma unroll
    for (int mi = 0; mi < 4; mi++) {
        int v = cr[mi];
        v += __shfl_xor_sync(0xFFFFFFFFu, v, 1);
        v += __shfl_xor_sync(0xFFFFFFFFu, v, 2);
        v += __shfl_xor_sync(0xFFFFFFFFu, v, 4);
        v += __shfl_xor_sync(0xFFFFFFFFu, v, 8);
        if (tx == 0) atomicAdd(&g_pa[rowBase + ty * 4 + mi], v);
    }

    if (offdiag) {
        #pragma unroll
        for (int ni = 0; ni < 4; ni++)
            if (cc[ni]) atomicAdd(&colCnt[tx * 4 + ni], cc[ni]);
    }

    #pragma unroll
    for (int o = 16; o; o >>= 1) {
        tsum += __shfl_xor_sync(0xFFFFFFFFu, tsum, o);
        nsum += __shfl_xor_sync(0xFFFFFFFFu, nsum, o);
        cnt  += __shfl_xor_sync(0xFFFFFFFFu, cnt,  o);
    }
    int wid = tid >> 5;
    if ((tid & 31) == 0) { redT[wid] = tsum; redN[wid] = nsum; redC[wid] = cnt; }
    __syncthreads();

    if (offdiag && tid < TN) {
        int v = colCnt[tid];
        if (v) atomicAdd(&g_pa[colBase + tid], v);
    }
    if (tid == 0) {
        float ts = 0.0f, ns = 0.0f; int cs = 0;
        #pragma unroll
        for (int w = 0; w < 8; w++) { ts += redT[w]; ns += redN[w]; cs += redC[w]; }
        atomicAdd(&g_tot, (double)ts);
        atomicAdd(&g_neg, (double)ns);
        atomicAdd(&g_nv, (unsigned long long)cs);
        __threadfence();
        unsigned int t = atomicAdd(&g_ticket, 1u);
        lastFlag[0] = (t == (unsigned int)(gridDim.x - 1)) ? 1 : 0;
    }
    __syncthreads();

    // --- Last block finalizes the 4 outputs ---
    if (lastFlag[0]) {
        __threadfence();
        int z = 0;
        for (int i2 = tid; i2 < n; i2 += THREADS) z += (g_pa[i2] == 0) ? 1 : 0;
        double ps = 0.0;
        for (int i2 = tid; i2 < n * 3; i2 += THREADS) ps += (double)(g_posp[i2] - MARGIN);
        zsh[tid] = z;
        psh[tid] = ps;
        __syncthreads();
        for (int s = 128; s; s >>= 1) {
            if (tid < s) { zsh[tid] += zsh[tid + s]; psh[tid] += psh[tid + s]; }
            __syncthreads();
        }
        if (tid == 0) {
            double nv = (double)g_nv;
            out[0] = (g_nv > 0ULL) ? (float)(g_tot / nv) : 0.0f;
            out[1] = (float)zsh[0] / (float)n;
            out[2] = (float)(psh[0] / ((double)n * (double)(K_INST - 1)));
            out[3] = (float)(g_neg / ((double)n * (double)(n - K_INST)));
        }
    }
}

// ---------------------------------------------------------------------------
extern "C" void kernel_launch(void* const* d_in, const int* in_sizes, int n_in,
                              void* d_out, int out_size) {
    const float* X = (const float*)d_in[0];
    int n = in_sizes[1];           // targets element count = n (4096)

    pos_kernel<<<(n * 32 + 255) / 256, 256>>>(X, n);
    main_kernel<<<NBLOCKS, THREADS>>>(X, (float*)d_out, n);
}

// round 10
// speedup vs baseline: 1.2047x; 1.2047x over previous
#include <cuda_runtime.h>
#include <math.h>

#define MARGIN 0.02f
#define EPS 1e-12f
#define K_INST 4
#define DIM 128
#define NMAX 4096

#define TM 128
#define TN 128
#define KC 16
#define ASTR 260      // duplicated-A k-row stride in floats (padded: 260%32=4)
#define BSTR 132      // B k-row stride in floats (padded)
#define TTILES 32     // n / TM
#define NBLOCKS 528   // TTILES*(TTILES+1)/2
#define THREADS 256

__device__ double g_tot;
__device__ double g_neg;
__device__ unsigned long long g_nv;
__device__ unsigned int g_ticket;
__device__ int   g_pa[NMAX];
__device__ float g_posp[NMAX * 3];    // pos_dist + MARGIN (plain stores, replay-safe)
__device__ float g_sqn[NMAX];

__device__ __forceinline__ float fsqrt_approx(float x) {
    float r;
    asm("sqrt.approx.f32 %0, %1;" : "=f"(r) : "f"(x));
    return r;
}

#define FFMA2(d, a, b, c) \
    asm("fma.rn.f32x2 %0, %1, %2, %3;" : "=l"(d) : "l"(a), "l"(b), "l"(c))

#define UNPACK2(lo, hi, v) \
    asm("mov.b64 {%0, %1}, %2;" : "=f"(lo), "=f"(hi) : "l"(v))

// ---------------------------------------------------------------------------
__global__ void pos_kernel(const float* __restrict__ X, int n) {
    int gwarp = (blockIdx.x * blockDim.x + threadIdx.x) >> 5;
    int lane  = threadIdx.x & 31;
    if (blockIdx.x == 0 && threadIdx.x == 0) {
        g_tot = 0.0; g_neg = 0.0; g_nv = 0ULL; g_ticket = 0u;
    }
    if (gwarp >= n) return;
    int i = gwarp;
    if (lane == 1) g_pa[i] = 0;

    float4 a = ((const float4*)(X + (size_t)i * DIM))[lane];
    float selfsq = a.x * a.x + a.y * a.y + a.z * a.z + a.w * a.w;

    int cs = i & ~(K_INST - 1);
    float dd[K_INST - 1];
    int idx = 0;
    #pragma unroll
    for (int q = 0; q < K_INST; q++) {
        if (cs + q == i) continue;
        float4 b = ((const float4*)(X + (size_t)(cs + q) * DIM))[lane];
        float dx = a.x - b.x, dy = a.y - b.y, dz = a.z - b.z, dw = a.w - b.w;
        dd[idx++] = dx * dx + dy * dy + dz * dz + dw * dw;
    }

    #pragma unroll
    for (int o = 16; o; o >>= 1) {
        selfsq += __shfl_xor_sync(0xFFFFFFFFu, selfsq, o);
        #pragma unroll
        for (int p = 0; p < K_INST - 1; p++)
            dd[p] += __shfl_xor_sync(0xFFFFFFFFu, dd[p], o);
    }

    if (lane == 0) {
        g_sqn[i] = selfsq;
        #pragma unroll
        for (int p = 0; p < K_INST - 1; p++) {
            float d = fsqrt_approx(fmaxf(dd[p], EPS));
            g_posp[i * 3 + p] = d + MARGIN;
        }
    }
}

// ---------------------------------------------------------------------------
// Upper-triangular 128x128 Gram tiles, 8x8 col-packed FFMA2 micro-tiles,
// UNSWIZZLED padded smem layout (immediate-offset LDS), fused epilogue.
__global__ __launch_bounds__(THREADS, 2) void main_kernel(const float* __restrict__ X,
                                                          float* __restrict__ out, int n) {
    // Triangular tile decode
    int bid = blockIdx.x;
    float tf = 2.0f * TTILES + 1.0f;
    int rowT = (int)((tf - sqrtf(tf * tf - 8.0f * (float)bid)) * 0.5f);
    while ((rowT + 1) * TTILES - ((rowT + 1) * rowT) / 2 <= bid) rowT++;
    while (rowT * TTILES - (rowT * (rowT - 1)) / 2 > bid) rowT--;
    int colT = rowT + (bid - (rowT * TTILES - (rowT * (rowT - 1)) / 2));

    __shared__ __align__(16) float AsD[KC * ASTR];   // ~16.6 KB, dup pairs (a,a)
    __shared__ __align__(16) float Bs[KC * BSTR];    //  ~8.4 KB
    __shared__ float sqA[TM];
    __shared__ float sqB[TN];
    __shared__ float ppA[TM][3];
    __shared__ float ppB[TN][3];
    __shared__ int   colCnt[TN];
    __shared__ float redT[8], redN[8];
    __shared__ int   redC[8];
    __shared__ int   lastFlag;
    __shared__ int   zsh[THREADS];
    __shared__ double psh[THREADS];

    int tid = threadIdx.x;
    int tx = tid & 15;       // n-dim (8 cols each)
    int ty = tid >> 4;       // m-dim (8 rows each)
    int rowBase = rowT * TM;
    int colBase = colT * TN;
    bool offdiag = (colT != rowT);

    if (tid < TM) sqA[tid] = g_sqn[rowBase + tid];
    else          sqB[tid - TM] = g_sqn[colBase + (tid - TM)];
    #pragma unroll
    for (int rep = 0; rep < 2; rep++) {
        int e = rep * THREADS + tid;
        if (e < TM * 3) {
            ((float*)ppA)[e] = g_posp[rowBase * 3 + e];
            ((float*)ppB)[e] = g_posp[colBase * 3 + e];
        }
    }
    if (tid < TN) colCnt[tid] = 0;

    unsigned long long acc[8][4];   // [row][colpair] packed (c0,c1)
    #pragma unroll
    for (int a = 0; a < 8; a++)
        #pragma unroll
        for (int b = 0; b < 4; b++) acc[a][b] = 0ULL;

    for (int kc = 0; kc < DIM; kc += KC) {
        // Load tiles: 128 rows x 16 k each -> 512 float4 per matrix.
        #pragma unroll
        for (int l = 0; l < 2; l++) {
            int idx = l * 256 + tid;
            int c4  = idx & 3;       // float4 index within 16-k chunk
            int row = idx >> 2;      // 0..127
            float4 v = *(const float4*)(X + (size_t)(rowBase + row) * DIM + kc + c4 * 4);
            float4 w = *(const float4*)(X + (size_t)(colBase + row) * DIM + kc + c4 * 4);
            #pragma unroll
            for (int q = 0; q < 4; q++) {
                int kk = c4 * 4 + q;
                float av = (&v.x)[q];
                // A dup: unit = row>>1 holds rows (2u, 2u+1) as (a,a) pairs
                *(float2*)&AsD[kk * ASTR + (row >> 1) * 4 + (row & 1) * 2] =
                    make_float2(av, av);
                // B: unit = row>>2 holds cols 4u..4u+3
                Bs[kk * BSTR + (row >> 2) * 4 + (row & 3)] = (&w.x)[q];
            }
        }
        __syncthreads();

        const float* aBase = &AsD[ty * 16];   // unit ty*4 => float offset ty*16
        const float* bBase = &Bs[tx * 8];     // unit tx*2 => float offset tx*8

        #pragma unroll
        for (int k = 0; k < KC; k++) {
            unsigned long long ap[8];
            #pragma unroll
            for (int j = 0; j < 4; j++) {
                ulonglong2 t = *(const ulonglong2*)(aBase + k * ASTR + j * 4);
                ap[j * 2 + 0] = t.x;
                ap[j * 2 + 1] = t.y;
            }
            unsigned long long bp[4];
            #pragma unroll
            for (int j = 0; j < 2; j++) {
                ulonglong2 t = *(const ulonglong2*)(bBase + k * BSTR + j * 4);
                bp[j * 2 + 0] = t.x;
                bp[j * 2 + 1] = t.y;
            }
            #pragma unroll
            for (int mi = 0; mi < 8; mi++) {
                FFMA2(acc[mi][0], ap[mi], bp[0], acc[mi][0]);
                FFMA2(acc[mi][1], ap[mi], bp[1], acc[mi][1]);
                FFMA2(acc[mi][2], ap[mi], bp[2], acc[mi][2]);
                FFMA2(acc[mi][3], ap[mi], bp[3], acc[mi][3]);
            }
        }
        __syncthreads();
    }

    // Unpack accumulators
    float accf[8][8];
    #pragma unroll
    for (int mi = 0; mi < 8; mi++)
        #pragma unroll
        for (int cj = 0; cj < 4; cj++)
            UNPACK2(accf[mi][cj * 2], accf[mi][cj * 2 + 1], acc[mi][cj]);

    // --- Fused epilogue ---
    float tsum = 0.0f, nsum = 0.0f;
    int cr[8], cc[8];
    #pragma unroll
    for (int z = 0; z < 8; z++) { cr[z] = 0; cc[z] = 0; }

    float qsq[8], qp0[8], qp1[8], qp2[8];
    #pragma unroll
    for (int ni = 0; ni < 8; ni++) {
        int nl = tx * 8 + ni;
        qsq[ni] = sqB[nl];
        qp0[ni] = ppB[nl][0];
        qp1[ni] = ppB[nl][1];
        qp2[ni] = ppB[nl][2];
    }

    #pragma unroll
    for (int mi = 0; mi < 8; mi++) {
        int m = ty * 8 + mi;
        int i = rowBase + m;
        int ci = i >> 2;
        float sqi = sqA[m];
        float pp0 = ppA[m][0], pp1 = ppA[m][1], pp2 = ppA[m][2];
        #pragma unroll
        for (int ni = 0; ni < 8; ni++) {
            int j = colBase + tx * 8 + ni;
            if (!offdiag && (j >> 2) == ci) continue;
            float d2 = sqi + qsq[ni] - 2.0f * accf[mi][ni];
            float d  = fsqrt_approx(fmaxf(d2, EPS));
            float t0 = pp0 - d, t1 = pp1 - d, t2 = pp2 - d;
            if (t0 > 0.0f) { tsum += t0; cr[mi]++; }
            if (t1 > 0.0f) { tsum += t1; cr[mi]++; }
            if (t2 > 0.0f) { tsum += t2; cr[mi]++; }
            if (offdiag) {
                nsum += 2.0f * d;
                float u0 = qp0[ni] - d, u1 = qp1[ni] - d, u2 = qp2[ni] - d;
                if (u0 > 0.0f) { tsum += u0; cc[ni]++; }
                if (u1 > 0.0f) { tsum += u1; cc[ni]++; }
                if (u2 > 0.0f) { tsum += u2; cc[ni]++; }
            } else {
                nsum += d;
            }
        }
    }

    int cnt = 0;
    #pragma unroll
    for (int z = 0; z < 8; z++) cnt += cr[z] + cc[z];

    // Row-anchor counts: reduce over the 16 tx lanes
    #pragma unroll
    for (int mi = 0; mi < 8; mi++) {
        int v = cr[mi];
        v += __shfl_xor_sync(0xFFFFFFFFu, v, 1);
        v += __shfl_xor_sync(0xFFFFFFFFu, v, 2);
        v += __shfl_xor_sync(0xFFFFFFFFu, v, 4);
        v += __shfl_xor_sync(0xFFFFFFFFu, v, 8);
        if (tx == 0) atomicAdd(&g_pa[rowBase + ty * 8 + mi], v);
    }

    if (offdiag) {
        #pragma unroll
        for (int ni = 0; ni < 8; ni++)
            if (cc[ni]) atomicAdd(&colCnt[tx * 8 + ni], cc[ni]);
    }

    #pragma unroll
    for (int o = 16; o; o >>= 1) {
        tsum += __shfl_xor_sync(0xFFFFFFFFu, tsum, o);
        nsum += __shfl_xor_sync(0xFFFFFFFFu, nsum, o);
        cnt  += __shfl_xor_sync(0xFFFFFFFFu, cnt,  o);
    }
    int wid = tid >> 5;
    if ((tid & 31) == 0) { redT[wid] = tsum; redN[wid] = nsum; redC[wid] = cnt; }
    __syncthreads();

    if (offdiag && tid < TN) {
        int v = colCnt[tid];
        if (v) atomicAdd(&g_pa[colBase + tid], v);
    }
    if (tid == 0) {
        float ts = 0.0f, ns = 0.0f; int cs = 0;
        #pragma unroll
        for (int w = 0; w < 8; w++) { ts += redT[w]; ns += redN[w]; cs += redC[w]; }
        atomicAdd(&g_tot, (double)ts);
        atomicAdd(&g_neg, (double)ns);
        atomicAdd(&g_nv, (unsigned long long)cs);
        __threadfence();
        unsigned int t = atomicAdd(&g_ticket, 1u);
        lastFlag = (t == (unsigned int)(gridDim.x - 1)) ? 1 : 0;
    }
    __syncthreads();

    // --- Last block finalizes the 4 outputs ---
    if (lastFlag) {
        __threadfence();
        int z = 0;
        for (int i2 = tid; i2 < n; i2 += THREADS) z += (g_pa[i2] == 0) ? 1 : 0;
        double ps = 0.0;
        for (int i2 = tid; i2 < n * 3; i2 += THREADS) ps += (double)(g_posp[i2] - MARGIN);
        zsh[tid] = z;
        psh[tid] = ps;
        __syncthreads();
        for (int s = THREADS / 2; s; s >>= 1) {
            if (tid < s) { zsh[tid] += zsh[tid + s]; psh[tid] += psh[tid + s]; }
            __syncthreads();
        }
        if (tid == 0) {
            double nv = (double)g_nv;
            out[0] = (g_nv > 0ULL) ? (float)(g_tot / nv) : 0.0f;
            out[1] = (float)zsh[0] / (float)n;
            out[2] = (float)(psh[0] / ((double)n * (double)(K_INST - 1)));
            out[3] = (float)(g_neg / ((double)n * (double)(n - K_INST)));
        }
    }
}

// ---------------------------------------------------------------------------
extern "C" void kernel_launch(void* const* d_in, const int* in_sizes, int n_in,
                              void* d_out, int out_size) {
    const float* X = (const float*)d_in[0];
    int n = in_sizes[1];           // targets element count = n (4096)

    pos_kernel<<<(n * 32 + 255) / 256, 256>>>(X, n);
    main_kernel<<<NBLOCKS, THREADS>>>(X, (float*)d_out, n);
}

// round 11
// speedup vs baseline: 1.8817x; 1.5620x over previous
#include <cuda_runtime.h>
#include <math.h>
#include <stdint.h>

#define MARGIN 0.02f
#define EPS 1e-12f
#define K_INST 4
#define DIM 128
#define NMAX 4096

#define TT 128          // tile edge
#define TTILES 32       // n / TT
#define NBLOCKS 528     // TTILES*(TTILES+1)/2
#define THREADS 256

__device__ double g_tot;
__device__ double g_neg;
__device__ unsigned long long g_nv;
__device__ unsigned int g_ticket;
__device__ int   g_pa[NMAX];
__device__ float g_posp[NMAX * 3];    // pos_dist + MARGIN (plain stores, replay-safe)
__device__ float g_sqn[NMAX];

__device__ __forceinline__ float fsqrt_approx(float x) {
    float r;
    asm("sqrt.approx.f32 %0, %1;" : "=f"(r) : "f"(x));
    return r;
}

__device__ __forceinline__ uint32_t f2tf32(float x) {
    uint32_t r;
    asm("cvt.rna.tf32.f32 %0, %1;" : "=r"(r) : "f"(x));
    return r;
}

#define MMA_TF32(c, a0, a1, a2, a3, b0, b1)                                    \
    asm volatile(                                                              \
        "mma.sync.aligned.m16n8k8.row.col.f32.tf32.tf32.f32 "                  \
        "{%0,%1,%2,%3}, {%4,%5,%6,%7}, {%8,%9}, {%0,%1,%2,%3};"                \
        : "+f"((c)[0]), "+f"((c)[1]), "+f"((c)[2]), "+f"((c)[3])               \
        : "r"(a0), "r"(a1), "r"(a2), "r"(a3), "r"(b0), "r"(b1))

// ---------------------------------------------------------------------------
__global__ void pos_kernel(const float* __restrict__ X, int n) {
    int gwarp = (blockIdx.x * blockDim.x + threadIdx.x) >> 5;
    int lane  = threadIdx.x & 31;
    if (blockIdx.x == 0 && threadIdx.x == 0) {
        g_tot = 0.0; g_neg = 0.0; g_nv = 0ULL; g_ticket = 0u;
    }
    if (gwarp >= n) return;
    int i = gwarp;
    if (lane == 1) g_pa[i] = 0;

    float4 a = ((const float4*)(X + (size_t)i * DIM))[lane];
    float selfsq = a.x * a.x + a.y * a.y + a.z * a.z + a.w * a.w;

    int cs = i & ~(K_INST - 1);
    float dd[K_INST - 1];
    int idx = 0;
    #pragma unroll
    for (int q = 0; q < K_INST; q++) {
        if (cs + q == i) continue;
        float4 b = ((const float4*)(X + (size_t)(cs + q) * DIM))[lane];
        float dx = a.x - b.x, dy = a.y - b.y, dz = a.z - b.z, dw = a.w - b.w;
        dd[idx++] = dx * dx + dy * dy + dz * dz + dw * dw;
    }

    #pragma unroll
    for (int o = 16; o; o >>= 1) {
        selfsq += __shfl_xor_sync(0xFFFFFFFFu, selfsq, o);
        #pragma unroll
        for (int p = 0; p < K_INST - 1; p++)
            dd[p] += __shfl_xor_sync(0xFFFFFFFFu, dd[p], o);
    }

    if (lane == 0) {
        g_sqn[i] = selfsq;
        #pragma unroll
        for (int p = 0; p < K_INST - 1; p++) {
            float d = fsqrt_approx(fmaxf(dd[p], EPS));
            g_posp[i * 3 + p] = d + MARGIN;
        }
    }
}

// ---------------------------------------------------------------------------
// Upper-triangular 128x128 Gram tiles via mma.sync TF32 (tensor pipe).
// 8 warps = 4 row-bands x 2 col-halves; warp = 2 m16 bands x 8 n8 tiles.
// Smem operands: (k, k+4) tf32 uint2 pairs -> 1 LDS.64 per fragment.
__global__ __launch_bounds__(THREADS, 2) void main_kernel(const float* __restrict__ X,
                                                          float* __restrict__ out, int n) {
    // Triangular tile decode
    int bid = blockIdx.x;
    float tf = 2.0f * TTILES + 1.0f;
    int rowT = (int)((tf - sqrtf(tf * tf - 8.0f * (float)bid)) * 0.5f);
    while ((rowT + 1) * TTILES - ((rowT + 1) * rowT) / 2 <= bid) rowT++;
    while (rowT * TTILES - (rowT * (rowT - 1)) / 2 > bid) rowT--;
    int colT = rowT + (bid - (rowT * TTILES - (rowT * (rowT - 1)) / 2));

    // [s][row][k4] uint2 = (tf32(k0+s*8+k4), tf32(k0+s*8+k4+4)), s=0..3, row=0..127
    __shared__ __align__(16) uint2 AsP[4 * 128 * 4];   // 16 KB
    __shared__ __align__(16) uint2 BsP[4 * 128 * 4];   // 16 KB
    __shared__ float sqB[TT];
    __shared__ float ppB[TT * 3];
    __shared__ int   colCnt[TT];
    __shared__ float redT[8], redN[8];
    __shared__ int   redC[8];
    __shared__ int   lastFlag;
    __shared__ int   zsh[THREADS];
    __shared__ double psh[THREADS];

    int tid  = threadIdx.x;
    int lane = tid & 31;
    int w    = tid >> 5;
    int wr   = w >> 1;        // row-band group 0..3 (32 rows each)
    int wc   = w & 1;         // col half 0..1 (64 cols each)
    int gr   = lane >> 2;     // 0..7
    int k4   = lane & 3;      // 0..3
    int rowBase = rowT * TT;
    int colBase = colT * TT;
    bool offdiag = (colT != rowT);

    if (tid < TT) { sqB[tid] = g_sqn[colBase + tid]; colCnt[tid] = 0; }
    #pragma unroll
    for (int rep = 0; rep < 2; rep++) {
        int e = rep * THREADS + tid;
        if (e < TT * 3) ppB[e] = g_posp[colBase * 3 + e];
    }

    float acc[2][8][4];
    #pragma unroll
    for (int b = 0; b < 2; b++)
        #pragma unroll
        for (int t = 0; t < 8; t++)
            #pragma unroll
            for (int q = 0; q < 4; q++) acc[b][t][q] = 0.0f;

    int m0 = wr * 32;

    for (int kc = 0; kc < DIM; kc += 32) {
        if (kc) __syncthreads();     // previous compute done before overwrite

        // Load + convert + store pair-layout: 1024 float4 per matrix, 4 iters
        #pragma unroll
        for (int it = 0; it < 4; it++) {
            int idx = it * 256 + tid;
            int row = idx >> 3;      // 0..127
            int c4  = idx & 7;       // float4 within 32-k chunk
            float4 v = *(const float4*)(X + (size_t)(rowBase + row) * DIM + kc + c4 * 4);
            float4 uv = *(const float4*)(X + (size_t)(colBase + row) * DIM + kc + c4 * 4);
            int s = c4 >> 1, h = c4 & 1;
            uint32_t* pA = (uint32_t*)&AsP[(s * 128 + row) * 4] + h;
            uint32_t* pB = (uint32_t*)&BsP[(s * 128 + row) * 4] + h;
            pA[0] = f2tf32(v.x); pA[2] = f2tf32(v.y);
            pA[4] = f2tf32(v.z); pA[6] = f2tf32(v.w);
            pB[0] = f2tf32(uv.x); pB[2] = f2tf32(uv.y);
            pB[4] = f2tf32(uv.z); pB[6] = f2tf32(uv.w);
        }
        __syncthreads();

        #pragma unroll
        for (int s = 0; s < 4; s++) {
            const uint2* Ab = &AsP[s * 512];
            const uint2* Bb = &BsP[s * 512 + wc * 64 * 4];
            uint2 fa0 = Ab[(m0 + gr) * 4 + k4];        // band0 rows gr / cols k4,k4+4
            uint2 fa1 = Ab[(m0 + gr + 8) * 4 + k4];
            uint2 fa2 = Ab[(m0 + 16 + gr) * 4 + k4];   // band1
            uint2 fa3 = Ab[(m0 + 24 + gr) * 4 + k4];
            #pragma unroll
            for (int t = 0; t < 8; t++) {
                uint2 fb = Bb[(t * 8 + gr) * 4 + k4];
                MMA_TF32(acc[0][t], fa0.x, fa1.x, fa0.y, fa1.y, fb.x, fb.y);
                MMA_TF32(acc[1][t], fa2.x, fa3.x, fa2.y, fa3.y, fb.x, fb.y);
            }
        }
    }

    // --- Fused epilogue ---
    // Thread owns rows Rl[b] (b = band*2 + q>>1) and cols wc*64 + t*8 + k4*2 + (q&1)
    int Rl[4];
    float sqa[4], pa3[4][3];
    #pragma unroll
    for (int b = 0; b < 4; b++) {
        Rl[b] = m0 + b * 8 + gr;     // gr, gr+8, gr+16, gr+24 (bands interleave as b0..b3)
        int gi = rowBase + Rl[b];
        sqa[b] = g_sqn[gi];
        pa3[b][0] = g_posp[gi * 3 + 0];
        pa3[b][1] = g_posp[gi * 3 + 1];
        pa3[b][2] = g_posp[gi * 3 + 2];
    }

    float tsum = 0.0f, nsum = 0.0f;
    int crow[4] = {0, 0, 0, 0};
    int ccol[16];
    #pragma unroll
    for (int e = 0; e < 16; e++) ccol[e] = 0;
    int cnt = 0;

    #pragma unroll
    for (int band = 0; band < 2; band++) {
        #pragma unroll
        for (int q = 0; q < 4; q++) {
            int b = band * 2 + (q >> 1);
            int rl = Rl[b];
            int gi = rowBase + rl;
            int ci = gi >> 2;
            float sqi = sqa[b];
            float pp0 = pa3[b][0], pp1 = pa3[b][1], pp2 = pa3[b][2];
            #pragma unroll
            for (int t = 0; t < 8; t++) {
                int cl = wc * 64 + t * 8 + k4 * 2 + (q & 1);
                int gj = colBase + cl;
                if (!offdiag && (gj >> 2) == ci) continue;
                float d2 = sqi + sqB[cl] - 2.0f * acc[band][t][q];
                float d  = fsqrt_approx(fmaxf(d2, EPS));
                float t0 = pp0 - d, t1 = pp1 - d, t2 = pp2 - d;
                if (t0 > 0.0f) { tsum += t0; crow[b]++; cnt++; }
                if (t1 > 0.0f) { tsum += t1; crow[b]++; cnt++; }
                if (t2 > 0.0f) { tsum += t2; crow[b]++; cnt++; }
                if (offdiag) {
                    nsum += 2.0f * d;
                    float u0 = ppB[cl * 3]     - d;
                    float u1 = ppB[cl * 3 + 1] - d;
                    float u2 = ppB[cl * 3 + 2] - d;
                    int e = t * 2 + (q & 1);
                    if (u0 > 0.0f) { tsum += u0; ccol[e]++; cnt++; }
                    if (u1 > 0.0f) { tsum += u1; ccol[e]++; cnt++; }
                    if (u2 > 0.0f) { tsum += u2; ccol[e]++; cnt++; }
                } else {
                    nsum += d;
                }
            }
        }
    }

    // Row-anchor counts: reduce over k4 (xor 1,2 stays within gr-group)
    #pragma unroll
    for (int b = 0; b < 4; b++) {
        int v = crow[b];
        v += __shfl_xor_sync(0xFFFFFFFFu, v, 1);
        v += __shfl_xor_sync(0xFFFFFFFFu, v, 2);
        if (k4 == 0 && v) atomicAdd(&g_pa[rowBase + Rl[b]], v);
    }

    // Col-anchor counts: reduce over gr (xor 4,8,16), lanes gr==0 flush to smem
    if (offdiag) {
        #pragma unroll
        for (int e = 0; e < 16; e++) {
            int v = ccol[e];
            v += __shfl_xor_sync(0xFFFFFFFFu, v, 4);
            v += __shfl_xor_sync(0xFFFFFFFFu, v, 8);
            v += __shfl_xor_sync(0xFFFFFFFFu, v, 16);
            if (gr == 0 && v)
                atomicAdd(&colCnt[wc * 64 + (e >> 1) * 8 + k4 * 2 + (e & 1)], v);
        }
    }

    #pragma unroll
    for (int o = 16; o; o >>= 1) {
        tsum += __shfl_xor_sync(0xFFFFFFFFu, tsum, o);
        nsum += __shfl_xor_sync(0xFFFFFFFFu, nsum, o);
        cnt  += __shfl_xor_sync(0xFFFFFFFFu, cnt,  o);
    }
    if (lane == 0) { redT[w] = tsum; redN[w] = nsum; redC[w] = cnt; }
    __syncthreads();

    if (offdiag && tid < TT) {
        int v = colCnt[tid];
        if (v) atomicAdd(&g_pa[colBase + tid], v);
    }
    if (tid == 0) {
        float ts = 0.0f, ns = 0.0f; int cs = 0;
        #pragma unroll
        for (int q = 0; q < 8; q++) { ts += redT[q]; ns += redN[q]; cs += redC[q]; }
        atomicAdd(&g_tot, (double)ts);
        atomicAdd(&g_neg, (double)ns);
        atomicAdd(&g_nv, (unsigned long long)cs);
        __threadfence();
        unsigned int t = atomicAdd(&g_ticket, 1u);
        lastFlag = (t == (unsigned int)(gridDim.x - 1)) ? 1 : 0;
    }
    __syncthreads();

    // --- Last block finalizes the 4 outputs ---
    if (lastFlag) {
        __threadfence();
        int z = 0;
        for (int i2 = tid; i2 < n; i2 += THREADS) z += (g_pa[i2] == 0) ? 1 : 0;
        double ps = 0.0;
        for (int i2 = tid; i2 < n * 3; i2 += THREADS) ps += (double)(g_posp[i2] - MARGIN);
        zsh[tid] = z;
        psh[tid] = ps;
        __syncthreads();
        for (int s = THREADS / 2; s; s >>= 1) {
            if (tid < s) { zsh[tid] += zsh[tid + s]; psh[tid] += psh[tid + s]; }
            __syncthreads();
        }
        if (tid == 0) {
            double nv = (double)g_nv;
            out[0] = (g_nv > 0ULL) ? (float)(g_tot / nv) : 0.0f;
            out[1] = (float)zsh[0] / (float)n;
            out[2] = (float)(psh[0] / ((double)n * (double)(K_INST - 1)));
            out[3] = (float)(g_neg / ((double)n * (double)(n - K_INST)));
        }
    }
}

// ---------------------------------------------------------------------------
extern "C" void kernel_launch(void* const* d_in, const int* in_sizes, int n_in,
                              void* d_out, int out_size) {
    const float* X = (const float*)d_in[0];
    int n = in_sizes[1];           // targets element count = n (4096)

    pos_kernel<<<(n * 32 + 255) / 256, 256>>>(X, n);
    main_kernel<<<NBLOCKS, THREADS>>>(X, (float*)d_out, n);
}

// round 12
// speedup vs baseline: 1.9597x; 1.0414x over previous
#include <cuda_runtime.h>
#include <math.h>
#include <stdint.h>

#define MARGIN 0.02f
#define EPS 1e-12f
#define K_INST 4
#define DIM 128
#define NMAX 4096

#define TT 128          // tile edge
#define TTILES 32       // n / TT
#define NBLOCKS 528     // TTILES*(TTILES+1)/2
#define THREADS 256

__device__ double g_tot;
__device__ double g_neg;
__device__ unsigned long long g_nv;
__device__ unsigned int g_ticket;
__device__ int   g_pa[NMAX];
__device__ float g_posp[NMAX * 3];    // pos_dist + MARGIN (plain stores, replay-safe)
__device__ float g_sqn[NMAX];

__device__ __forceinline__ float fsqrt_approx(float x) {
    float r;
    asm("sqrt.approx.f32 %0, %1;" : "=f"(r) : "f"(x));
    return r;
}

#define MMA_TF32(c, a0, a1, a2, a3, b0, b1)                                    \
    asm volatile(                                                              \
        "mma.sync.aligned.m16n8k8.row.col.f32.tf32.tf32.f32 "                  \
        "{%0,%1,%2,%3}, {%4,%5,%6,%7}, {%8,%9}, {%0,%1,%2,%3};"                \
        : "+f"((c)[0]), "+f"((c)[1]), "+f"((c)[2]), "+f"((c)[3])               \
        : "r"(a0), "r"(a1), "r"(a2), "r"(a3), "r"(b0), "r"(b1))

// ---------------------------------------------------------------------------
__global__ void pos_kernel(const float* __restrict__ X, int n) {
    int gwarp = (blockIdx.x * blockDim.x + threadIdx.x) >> 5;
    int lane  = threadIdx.x & 31;
    if (blockIdx.x == 0 && threadIdx.x == 0) {
        g_tot = 0.0; g_neg = 0.0; g_nv = 0ULL; g_ticket = 0u;
    }
    if (gwarp >= n) return;
    int i = gwarp;
    if (lane == 1) g_pa[i] = 0;

    float4 a = ((const float4*)(X + (size_t)i * DIM))[lane];
    float selfsq = a.x * a.x + a.y * a.y + a.z * a.z + a.w * a.w;

    int cs = i & ~(K_INST - 1);
    float dd[K_INST - 1];
    int idx = 0;
    #pragma unroll
    for (int q = 0; q < K_INST; q++) {
        if (cs + q == i) continue;
        float4 b = ((const float4*)(X + (size_t)(cs + q) * DIM))[lane];
        float dx = a.x - b.x, dy = a.y - b.y, dz = a.z - b.z, dw = a.w - b.w;
        dd[idx++] = dx * dx + dy * dy + dz * dz + dw * dw;
    }

    #pragma unroll
    for (int o = 16; o; o >>= 1) {
        selfsq += __shfl_xor_sync(0xFFFFFFFFu, selfsq, o);
        #pragma unroll
        for (int p = 0; p < K_INST - 1; p++)
            dd[p] += __shfl_xor_sync(0xFFFFFFFFu, dd[p], o);
    }

    if (lane == 0) {
        g_sqn[i] = selfsq;
        #pragma unroll
        for (int p = 0; p < K_INST - 1; p++) {
            float d = fsqrt_approx(fmaxf(dd[p], EPS));
            g_posp[i * 3 + p] = d + MARGIN;
        }
    }
}

// ---------------------------------------------------------------------------
// Upper-triangular 128x128 Gram tiles via mma.sync TF32 (raw-bit truncation).
// Smem layout per matrix (16 KB): addr(row,s,k4) = row*128 + (s^(row&3))*32
// + k4*8 bytes, holding uint2 pair (k = s*8+k4, k = s*8+k4+4).
// Fragment LDS.64 reads are bank-conflict-free; stores are 2xSTS.128.
__global__ __launch_bounds__(THREADS, 2) void main_kernel(const float* __restrict__ X,
                                                          float* __restrict__ out, int n) {
    // Triangular tile decode
    int bid = blockIdx.x;
    float tf = 2.0f * TTILES + 1.0f;
    int rowT = (int)((tf - sqrtf(tf * tf - 8.0f * (float)bid)) * 0.5f);
    while ((rowT + 1) * TTILES - ((rowT + 1) * rowT) / 2 <= bid) rowT++;
    while (rowT * TTILES - (rowT * (rowT - 1)) / 2 > bid) rowT--;
    int colT = rowT + (bid - (rowT * TTILES - (rowT * (rowT - 1)) / 2));

    __shared__ __align__(16) char As[128 * 128];    // 16 KB
    __shared__ __align__(16) char Bs[128 * 128];    // 16 KB
    __shared__ float sqB[TT];
    __shared__ float ppB[TT * 3];
    __shared__ int   colCnt[TT];
    __shared__ float redT[8], redN[8];
    __shared__ int   redC[8];
    __shared__ int   lastFlag;
    __shared__ int   zsh[THREADS];
    __shared__ double psh[THREADS];

    int tid  = threadIdx.x;
    int lane = tid & 31;
    int w    = tid >> 5;
    int wr   = w >> 1;        // row-band group 0..3 (32 rows each)
    int wc   = w & 1;         // col half 0..1 (64 cols each)
    int gr   = lane >> 2;     // 0..7
    int k4   = lane & 3;      // 0..3
    int rowBase = rowT * TT;
    int colBase = colT * TT;
    bool offdiag = (colT != rowT);

    if (tid < TT) { sqB[tid] = g_sqn[colBase + tid]; colCnt[tid] = 0; }
    #pragma unroll
    for (int rep = 0; rep < 2; rep++) {
        int e = rep * THREADS + tid;
        if (e < TT * 3) ppB[e] = g_posp[colBase * 3 + e];
    }

    float acc[2][8][4];
    #pragma unroll
    for (int b = 0; b < 2; b++)
        #pragma unroll
        for (int t = 0; t < 8; t++)
            #pragma unroll
            for (int q = 0; q < 4; q++) acc[b][t][q] = 0.0f;

    int m0 = wr * 32;
    int grm = gr & 3;

    // Loader coords: 2 (row, c2) groups per thread per stage per matrix
    int row0 = tid >> 2;          // 0..63  (it=0), +64 (it=1)
    int c2   = tid & 3;           // k-chunk 0..3 within 32-k stage

    for (int kc = 0; kc < DIM; kc += 32) {
        if (kc) __syncthreads();

        #pragma unroll
        for (int it = 0; it < 2; it++) {
            int row = row0 + it * 64;
            const float* pA = X + (size_t)(rowBase + row) * DIM + kc + c2 * 8;
            const float* pB = X + (size_t)(colBase + row) * DIM + kc + c2 * 8;
            float4 v = *(const float4*)pA;
            float4 vw = *(const float4*)(pA + 4);
            float4 u = *(const float4*)pB;
            float4 uw = *(const float4*)(pB + 4);
            uint32_t base = (uint32_t)(row * 128 + ((c2 ^ (row & 3)) * 32));
            *(uint4*)(As + base) = make_uint4(
                __float_as_uint(v.x), __float_as_uint(vw.x),
                __float_as_uint(v.y), __float_as_uint(vw.y));
            *(uint4*)(As + base + 16) = make_uint4(
                __float_as_uint(v.z), __float_as_uint(vw.z),
                __float_as_uint(v.w), __float_as_uint(vw.w));
            *(uint4*)(Bs + base) = make_uint4(
                __float_as_uint(u.x), __float_as_uint(uw.x),
                __float_as_uint(u.y), __float_as_uint(uw.y));
            *(uint4*)(Bs + base + 16) = make_uint4(
                __float_as_uint(u.z), __float_as_uint(uw.z),
                __float_as_uint(u.w), __float_as_uint(uw.w));
        }
        __syncthreads();

        #pragma unroll
        for (int s = 0; s < 4; s++) {
            uint32_t xs = (uint32_t)(((s ^ grm) * 32) + k4 * 8);
            const char* aB = As + (m0 + gr) * 128 + xs;
            const char* bB = Bs + (wc * 64 + gr) * 128 + xs;
            uint2 fa0 = *(const uint2*)(aB);
            uint2 fa1 = *(const uint2*)(aB + 8 * 128);
            uint2 fa2 = *(const uint2*)(aB + 16 * 128);
            uint2 fa3 = *(const uint2*)(aB + 24 * 128);
            #pragma unroll
            for (int t = 0; t < 8; t++) {
                uint2 fb = *(const uint2*)(bB + t * 1024);
                MMA_TF32(acc[0][t], fa0.x, fa1.x, fa0.y, fa1.y, fb.x, fb.y);
                MMA_TF32(acc[1][t], fa2.x, fa3.x, fa2.y, fa3.y, fb.x, fb.y);
            }
        }
    }

    // --- Fused epilogue ---
    int Rl[4];
    float sqa[4], pa3[4][3];
    #pragma unroll
    for (int b = 0; b < 4; b++) {
        Rl[b] = m0 + b * 8 + gr;
        int gi = rowBase + Rl[b];
        sqa[b] = g_sqn[gi];
        pa3[b][0] = g_posp[gi * 3 + 0];
        pa3[b][1] = g_posp[gi * 3 + 1];
        pa3[b][2] = g_posp[gi * 3 + 2];
    }

    float tsum = 0.0f, nsum = 0.0f;
    int crow[4] = {0, 0, 0, 0};
    int ccol[16];
    #pragma unroll
    for (int e = 0; e < 16; e++) ccol[e] = 0;
    int cnt = 0;

    #pragma unroll
    for (int band = 0; band < 2; band++) {
        #pragma unroll
        for (int q = 0; q < 4; q++) {
            int b = band * 2 + (q >> 1);
            int gi = rowBase + Rl[b];
            int ci = gi >> 2;
            float sqi = sqa[b];
            float pp0 = pa3[b][0], pp1 = pa3[b][1], pp2 = pa3[b][2];
            #pragma unroll
            for (int t = 0; t < 8; t++) {
                int cl = wc * 64 + t * 8 + k4 * 2 + (q & 1);
                int gj = colBase + cl;
                if (!offdiag && (gj >> 2) == ci) continue;
                float d2 = sqi + sqB[cl] - 2.0f * acc[band][t][q];
                float d  = fsqrt_approx(fmaxf(d2, EPS));
                float t0 = pp0 - d, t1 = pp1 - d, t2 = pp2 - d;
                if (t0 > 0.0f) { tsum += t0; crow[b]++; cnt++; }
                if (t1 > 0.0f) { tsum += t1; crow[b]++; cnt++; }
                if (t2 > 0.0f) { tsum += t2; crow[b]++; cnt++; }
                if (offdiag) {
                    nsum += 2.0f * d;
                    float u0 = ppB[cl * 3]     - d;
                    float u1 = ppB[cl * 3 + 1] - d;
                    float u2 = ppB[cl * 3 + 2] - d;
                    int e = t * 2 + (q & 1);
                    if (u0 > 0.0f) { tsum += u0; ccol[e]++; cnt++; }
                    if (u1 > 0.0f) { tsum += u1; ccol[e]++; cnt++; }
                    if (u2 > 0.0f) { tsum += u2; ccol[e]++; cnt++; }
                } else {
                    nsum += d;
                }
            }
        }
    }

    // Row-anchor counts: reduce over k4
    #pragma unroll
    for (int b = 0; b < 4; b++) {
        int v = crow[b];
        v += __shfl_xor_sync(0xFFFFFFFFu, v, 1);
        v += __shfl_xor_sync(0xFFFFFFFFu, v, 2);
        if (k4 == 0 && v) atomicAdd(&g_pa[rowBase + Rl[b]], v);
    }

    // Col-anchor counts: reduce over gr
    if (offdiag) {
        #pragma unroll
        for (int e = 0; e < 16; e++) {
            int v = ccol[e];
            v += __shfl_xor_sync(0xFFFFFFFFu, v, 4);
            v += __shfl_xor_sync(0xFFFFFFFFu, v, 8);
            v += __shfl_xor_sync(0xFFFFFFFFu, v, 16);
            if (gr == 0 && v)
                atomicAdd(&colCnt[wc * 64 + (e >> 1) * 8 + k4 * 2 + (e & 1)], v);
        }
    }

    #pragma unroll
    for (int o = 16; o; o >>= 1) {
        tsum += __shfl_xor_sync(0xFFFFFFFFu, tsum, o);
        nsum += __shfl_xor_sync(0xFFFFFFFFu, nsum, o);
        cnt  += __shfl_xor_sync(0xFFFFFFFFu, cnt,  o);
    }
    if (lane == 0) { redT[w] = tsum; redN[w] = nsum; redC[w] = cnt; }
    __syncthreads();

    if (offdiag && tid < TT) {
        int v = colCnt[tid];
        if (v) atomicAdd(&g_pa[colBase + tid], v);
    }
    if (tid == 0) {
        float ts = 0.0f, ns = 0.0f; int cs = 0;
        #pragma unroll
        for (int q = 0; q < 8; q++) { ts += redT[q]; ns += redN[q]; cs += redC[q]; }
        atomicAdd(&g_tot, (double)ts);
        atomicAdd(&g_neg, (double)ns);
        atomicAdd(&g_nv, (unsigned long long)cs);
        __threadfence();
        unsigned int t = atomicAdd(&g_ticket, 1u);
        lastFlag = (t == (unsigned int)(gridDim.x - 1)) ? 1 : 0;
    }
    __syncthreads();

    // --- Last block finalizes the 4 outputs ---
    if (lastFlag) {
        __threadfence();
        int z = 0;
        for (int i2 = tid; i2 < n; i2 += THREADS) z += (g_pa[i2] == 0) ? 1 : 0;
        double ps = 0.0;
        for (int i2 = tid; i2 < n * 3; i2 += THREADS) ps += (double)(g_posp[i2] - MARGIN);
        zsh[tid] = z;
        psh[tid] = ps;
        __syncthreads();
        for (int s = THREADS / 2; s; s >>= 1) {
            if (tid < s) { zsh[tid] += zsh[tid + s]; psh[tid] += psh[tid + s]; }
            __syncthreads();
        }
        if (tid == 0) {
            double nv = (double)g_nv;
            out[0] = (g_nv > 0ULL) ? (float)(g_tot / nv) : 0.0f;
            out[1] = (float)zsh[0] / (float)n;
            out[2] = (float)(psh[0] / ((double)n * (double)(K_INST - 1)));
            out[3] = (float)(g_neg / ((double)n * (double)(n - K_INST)));
        }
    }
}

// ---------------------------------------------------------------------------
extern "C" void kernel_launch(void* const* d_in, const int* in_sizes, int n_in,
                              void* d_out, int out_size) {
    const float* X = (const float*)d_in[0];
    int n = in_sizes[1];           // targets element count = n (4096)

    pos_kernel<<<(n * 32 + 255) / 256, 256>>>(X, n);
    main_kernel<<<NBLOCKS, THREADS>>>(X, (float*)d_out, n);
}